// round 12
// baseline (speedup 1.0000x reference)
#include <cuda_runtime.h>
#include <math.h>

#define N0 78400      // B*28*28
#define N1 19600      // B*14*14
#define E0 627200
#define E1 156800
#define C1 32
#define C2 64
#define TW 26         // 25 tap cols + 1 degree col
#define SK 800        // S row width: 25 taps * 32 cin

__device__ float g_T[N0 * TW];             // layer-1 tap accumulator (+deg)
__device__ float g_pool1[N1 * C1];
__device__ float g_S[N1 * SK];             // layer-2 scattered tap features
__device__ float g_agg1[N1 * C2];          // gemmS output (deg-divided, root added)
__device__ float g_deg1[N1];
__device__ float g_fc1[100 * 512];

__device__ __forceinline__ float elu1(float v) {
    return v > 0.f ? v : (expf(v) - 1.f);
}

// ---- packed f32x2 helpers (sm_100+) ----
__device__ __forceinline__ void ffma2(unsigned long long &d,
                                      unsigned long long a,
                                      unsigned long long b) {
    asm("fma.rn.f32x2 %0, %1, %2, %0;" : "+l"(d) : "l"(a), "l"(b));
}
__device__ __forceinline__ unsigned long long dup2(float v) {
    unsigned long long r; unsigned int u = __float_as_uint(v);
    asm("mov.b64 %0, {%1, %1};" : "=l"(r) : "r"(u));
    return r;
}
__device__ __forceinline__ float2 ull2f2(unsigned long long u) {
    float2 r;
    asm("mov.b64 {%0, %1}, %2;" : "=f"(r.x), "=f"(r.y) : "l"(u));
    return r;
}
// Vectored no-return reduction (sm_90+): 8B atomic add of a float pair.
__device__ __forceinline__ void red_add_v2(float* p, float a, float b) {
    asm volatile("red.global.add.v2.f32 [%0], {%1, %2};"
                 :: "l"(p), "f"(a), "f"(b) : "memory");
}

// Zero only T (needed before edge1). S/deg1/fc1 zeroing rides in pool1's tail.
__global__ void zeroT_kernel() {
    int stride = gridDim.x * blockDim.x;
    int t0 = blockIdx.x * blockDim.x + threadIdx.x;
    float4 z = make_float4(0.f, 0.f, 0.f, 0.f);
    float4* T4 = (float4*)g_T;
    for (int i = t0; i < (N0 * TW) / 4; i += stride) T4[i] = z;
}

// Layer-1 edges, factorized (Cin=1): scatter x[s]-scaled tap weights into T[dst].
__global__ void edge1_kernel(const float* __restrict__ x,
                             const int* __restrict__ ei,
                             const float* __restrict__ ps) {
    int e = blockIdx.x * blockDim.x + threadIdx.x;
    if (e >= E0) return;
    int s = ei[e];
    int d = ei[E0 + e];
    float xv = __ldg(x + s);
    float2 pv = ((const float2*)ps)[e];
    float px = pv.x * 4.f;
    float py = pv.y * 4.f;
    float fxf = floorf(px), fyf = floorf(py);
    float fx = px - fxf, fy = py - fyf;
    int kx0 = min((int)fxf, 4), ky0 = min((int)fyf, 4);
    int kx1 = min(kx0 + 1, 4), ky1 = min(ky0 + 1, 4);
    float* Tb = g_T + d * TW;
    atomicAdd(Tb + kx0 * 5 + ky0, xv * (1.f - fx) * (1.f - fy));
    atomicAdd(Tb + kx0 * 5 + ky1, xv * (1.f - fx) * fy);
    atomicAdd(Tb + kx1 * 5 + ky0, xv * fx * (1.f - fy));
    atomicAdd(Tb + kx1 * 5 + ky1, xv * fx * fy);
    atomicAdd(Tb + 25, 1.f);
}

// Fused: T@W1 (25x32) + deg-normalize + root + bias + 2x2 maxpool + ELU -> pool1
// Tail: zero S, deg1, fc1 (grid-stride; exactly N1*C1 = 627200 threads).
__global__ void pool1_kernel(const float* __restrict__ x,
                             const float* __restrict__ W1,
                             const float* __restrict__ root1,
                             const float* __restrict__ b1) {
    __shared__ float sW[25 * C1];
    for (int i = threadIdx.x; i < 25 * C1; i += blockDim.x) sW[i] = W1[i];
    __syncthreads();

    int tid = blockIdx.x * blockDim.x + threadIdx.x;   // grid is exact
    int ch = tid & 31;
    int p = tid >> 5;
    int pc = p % 14;
    int pr = (p / 14) % 14;
    int b = p / 196;
    float r1 = root1[ch];
    float bias = b1[ch];
    float m = -1e30f;
#pragma unroll
    for (int dr = 0; dr < 2; dr++)
#pragma unroll
        for (int dc = 0; dc < 2; dc++) {
            int n = b * 784 + (2 * pr + dr) * 28 + (2 * pc + dc);
            const float* Tr = g_T + n * TW;
            float deg = fmaxf(Tr[25], 1.f);
            float acc = 0.f;
#pragma unroll
            for (int k = 0; k < 25; k++) acc += Tr[k] * sW[k * C1 + ch];
            float v = acc / deg + x[n] * r1 + bias;
            m = fmaxf(m, v);
        }
    g_pool1[p * C1 + ch] = elu1(m);

    // ---- zero tails (S, deg1, fc1) ----
    int stride = gridDim.x * blockDim.x;
    float4 z = make_float4(0.f, 0.f, 0.f, 0.f);
    float4* S4 = (float4*)g_S;
    float4* D4 = (float4*)g_deg1;
    float4* F4 = (float4*)g_fc1;
    for (int i = tid; i < (N1 * SK) / 4; i += stride) S4[i] = z;
    for (int i = tid; i < N1 / 4; i += stride) D4[i] = z;
    for (int i = tid; i < (100 * 512) / 4; i += stride) F4[i] = z;
}

// Layer-2 edges: 16 threads per edge, thread = cin pair. Scatter tap-weighted
// pool1[src] rows into S[dst] via red.v2 (half the REDG issue of scalar).
__global__ void scatter2_kernel(const int* __restrict__ ei,
                                const float* __restrict__ ps) {
    int gt = blockIdx.x * blockDim.x + threadIdx.x;
    int e = gt >> 4;
    int h = gt & 15;          // cin pair index: channels 2h, 2h+1
    if (e >= E1) return;
    int s = ei[e];
    int d = ei[E1 + e];
    float2 pv = ((const float2*)ps)[e];
    float px = pv.x * 4.f;
    float py = pv.y * 4.f;
    float fxf = floorf(px), fyf = floorf(py);
    float fx = px - fxf, fy = py - fyf;
    int kx0 = min((int)fxf, 4), ky0 = min((int)fyf, 4);
    int kx1 = min(kx0 + 1, 4), ky1 = min(ky0 + 1, 4);
    float w00 = (1.f - fx) * (1.f - fy);
    float w01 = (1.f - fx) * fy;
    float w10 = fx * (1.f - fy);
    float w11 = fx * fy;
    float2 xv = *(const float2*)(g_pool1 + s * C1 + 2 * h);
    float* Sb = g_S + d * SK + 2 * h;
    red_add_v2(Sb + (kx0 * 5 + ky0) * 32, xv.x * w00, xv.y * w00);
    red_add_v2(Sb + (kx0 * 5 + ky1) * 32, xv.x * w01, xv.y * w01);
    red_add_v2(Sb + (kx1 * 5 + ky0) * 32, xv.x * w10, xv.y * w10);
    red_add_v2(Sb + (kx1 * 5 + ky1) * 32, xv.x * w11, xv.y * w11);
    if (h == 0) atomicAdd(&g_deg1[d], 1.f);
}

// agg1[19600x64] = S[19600x800] @ W2flat[800x64] / deg + pool1 @ root2
// m-tile 64, 256 threads, thread = 4m x 4n, packed f32x2 FMA.
__global__ void __launch_bounds__(256) gemmS_kernel(const float* __restrict__ W2,
                                                    const float* __restrict__ root2) {
    __shared__ float As[32 * 68];   // [k][m], stride 68 (16B-aligned rows)
    __shared__ float Bs[32 * 64];   // [k][n]
    int tid = threadIdx.x;
    int m0 = blockIdx.x * 64;
    int tm = tid >> 4;       // 0..15 -> m rows tm*4..tm*4+3
    int tn = tid & 15;       // 0..15 -> n cols tn*4..tn*4+3

    unsigned long long accm[2][4], accr[2][4];
#pragma unroll
    for (int p = 0; p < 2; p++)
#pragma unroll
        for (int j = 0; j < 4; j++) { accm[p][j] = 0ull; accr[p][j] = 0ull; }

    // 25 chunks over S/W2, then 1 chunk over pool1/root2 (into accr).
    for (int c = 0; c < 26; c++) {
        __syncthreads();
        if (c < 25) {
            int k0 = c * 32;
            for (int idx = tid; idx < 64 * 32; idx += 256) {
                int r = idx >> 5, k = idx & 31;
                int row = min(m0 + r, N1 - 1);
                As[k * 68 + r] = g_S[row * SK + k0 + k];
            }
            for (int idx = tid; idx < 32 * 64; idx += 256) {
                int k = idx >> 6, nn = idx & 63;
                Bs[k * 64 + nn] = W2[(k0 + k) * 64 + nn];
            }
        } else {
            for (int idx = tid; idx < 64 * 32; idx += 256) {
                int r = idx >> 5, k = idx & 31;
                int row = min(m0 + r, N1 - 1);
                As[k * 68 + r] = g_pool1[row * C1 + k];
            }
            for (int idx = tid; idx < 32 * 64; idx += 256) {
                int k = idx >> 6, nn = idx & 63;
                Bs[k * 64 + nn] = root2[k * 64 + nn];
            }
        }
        __syncthreads();
        unsigned long long (*acc)[4] = (c < 25) ? accm : accr;
#pragma unroll
        for (int k = 0; k < 32; k++) {
            ulonglong2 a = *(const ulonglong2*)&As[k * 68 + tm * 4];
            float4 b = *(const float4*)&Bs[k * 64 + tn * 4];
            unsigned long long bd[4] = {dup2(b.x), dup2(b.y), dup2(b.z), dup2(b.w)};
#pragma unroll
            for (int j = 0; j < 4; j++) {
                ffma2(acc[0][j], a.x, bd[j]);
                ffma2(acc[1][j], a.y, bd[j]);
            }
        }
    }

    // epilogue: rows tm*4+2p (lo) and tm*4+2p+1 (hi); out = accm/deg + accr
#pragma unroll
    for (int p = 0; p < 2; p++) {
        int r0 = m0 + tm * 4 + 2 * p;
        if (r0 >= N1) break;
        float d0 = 1.f / fmaxf(g_deg1[r0], 1.f);
        float d1 = (r0 + 1 < N1) ? 1.f / fmaxf(g_deg1[r0 + 1], 1.f) : 1.f;
        float2 m0f = ull2f2(accm[p][0]), m1f = ull2f2(accm[p][1]);
        float2 m2f = ull2f2(accm[p][2]), m3f = ull2f2(accm[p][3]);
        float2 r0f = ull2f2(accr[p][0]), r1f = ull2f2(accr[p][1]);
        float2 r2f = ull2f2(accr[p][2]), r3f = ull2f2(accr[p][3]);
        float4 lo = make_float4(m0f.x * d0 + r0f.x, m1f.x * d0 + r1f.x,
                                m2f.x * d0 + r2f.x, m3f.x * d0 + r3f.x);
        float4 hi = make_float4(m0f.y * d1 + r0f.y, m1f.y * d1 + r1f.y,
                                m2f.y * d1 + r2f.y, m3f.y * d1 + r3f.y);
        *(float4*)&g_agg1[r0 * C2 + tn * 4] = lo;
        if (r0 + 1 < N1)
            *(float4*)&g_agg1[(r0 + 1) * C2 + tn * 4] = hi;
    }
}

// fc1 with fused pool2: input element (m, k) is computed on the fly as
// elu(max over 2x2 agg1 nodes + b2). M=100, N=512, K=3136, k-split atomics.
__global__ void fc1_kernel(const float* __restrict__ w,
                           const float* __restrict__ b2) {
    __shared__ float sin_s[100 * 56];
    __shared__ float sw_s[56 * 32];
    int tid = threadIdx.x;
    int jl = tid & 31;
    int mg = tid >> 5;
    int j0 = blockIdx.x * 32;
    int kbase = blockIdx.y * 392;

    float acc[13];
#pragma unroll
    for (int i = 0; i < 13; i++) acc[i] = 0.f;

    for (int c = 0; c < 7; c++) {
        int k0 = kbase + c * 56;
        __syncthreads();
        // fused pool2: sin_s[m][kk] = elu(max_{2x2} agg1 + b2)
        for (int idx = tid; idx < 100 * 56; idx += 256) {
            int m = idx / 56, kk = idx % 56;
            int k = k0 + kk;
            int p = m * 49 + (k >> 6);       // pooled position 0..4899
            int ch = k & 63;
            int pc = p % 14;
            int pr = (p / 14) % 14;
            int bb = p / 196;
            int nb = bb * 784 + 2 * pr * 28 + 2 * pc;
            float v0 = g_agg1[nb * C2 + ch];
            float v1 = g_agg1[(nb + 1) * C2 + ch];
            float v2 = g_agg1[(nb + 28) * C2 + ch];
            float v3 = g_agg1[(nb + 29) * C2 + ch];
            float mx = fmaxf(fmaxf(v0, v1), fmaxf(v2, v3)) + b2[ch];
            sin_s[idx] = elu1(mx);
        }
        for (int idx = tid; idx < 56 * 32; idx += 256) {
            int kk = idx >> 5, jj = idx & 31;
            sw_s[idx] = w[(k0 + kk) * 512 + j0 + jj];
        }
        __syncthreads();
#pragma unroll
        for (int q = 0; q < 14; q++) {
            float w0 = sw_s[(q * 4 + 0) * 32 + jl];
            float w1 = sw_s[(q * 4 + 1) * 32 + jl];
            float w2 = sw_s[(q * 4 + 2) * 32 + jl];
            float w3 = sw_s[(q * 4 + 3) * 32 + jl];
#pragma unroll
            for (int mi = 0; mi < 13; mi++) {
                int m = mg * 13 + mi;
                float4 s4 = *(const float4*)&sin_s[m * 56 + q * 4];
                acc[mi] += s4.x * w0 + s4.y * w1 + s4.z * w2 + s4.w * w3;
            }
        }
    }
#pragma unroll
    for (int mi = 0; mi < 13; mi++) {
        int m = mg * 13 + mi;
        if (m < 100) atomicAdd(&g_fc1[m * 512 + j0 + jl], acc[mi]);
    }
}

// Block per batch row: stage elu(fc1+bias) in smem, 10 warps -> logits, log_softmax.
__global__ void fc2_kernel(const float* __restrict__ b1v,
                           const float* __restrict__ w,
                           const float* __restrict__ b,
                           float* __restrict__ out) {
    __shared__ float sx[512];
    __shared__ float sh[10];
    int m = blockIdx.x;
    int tid = threadIdx.x;
    for (int i = tid; i < 512; i += 320)
        sx[i] = elu1(g_fc1[m * 512 + i] + b1v[i]);
    __syncthreads();
    int warp = tid >> 5;
    int lane = tid & 31;
    if (warp < 10) {
        float acc = 0.f;
        for (int i = lane; i < 512; i += 32)
            acc += sx[i] * w[i * 10 + warp];
#pragma unroll
        for (int o = 16; o > 0; o >>= 1)
            acc += __shfl_down_sync(0xffffffffu, acc, o);
        if (lane == 0) sh[warp] = elu1(acc + b[warp]);
    }
    __syncthreads();
    if (tid == 0) {
        float mx = sh[0];
        for (int c = 1; c < 10; c++) mx = fmaxf(mx, sh[c]);
        float s = 0.f;
        for (int c = 0; c < 10; c++) s += expf(sh[c] - mx);
        float lse = mx + logf(s);
        for (int c = 0; c < 10; c++) out[m * 10 + c] = sh[c] - lse;
    }
}

extern "C" void kernel_launch(void* const* d_in, const int* in_sizes, int n_in,
                              void* d_out, int out_size) {
    const float* x       = (const float*)d_in[0];
    const float* pseudo0 = (const float*)d_in[1];
    const float* pseudo1 = (const float*)d_in[2];
    const float* W1      = (const float*)d_in[3];
    const float* root1   = (const float*)d_in[4];
    const float* b1      = (const float*)d_in[5];
    const float* W2      = (const float*)d_in[6];
    const float* root2   = (const float*)d_in[7];
    const float* b2      = (const float*)d_in[8];
    const float* fc1_w   = (const float*)d_in[9];
    const float* fc1_b   = (const float*)d_in[10];
    const float* fc2_w   = (const float*)d_in[11];
    const float* fc2_b   = (const float*)d_in[12];
    const int* ei0       = (const int*)d_in[13];
    const int* ei1       = (const int*)d_in[14];
    float* out = (float*)d_out;

    zeroT_kernel<<<512, 256>>>();
    edge1_kernel<<<(E0 + 255) / 256, 256>>>(x, ei0, pseudo0);
    pool1_kernel<<<(N1 * C1) / 256, 256>>>(x, W1, root1, b1);
    scatter2_kernel<<<(E1 * 16 + 255) / 256, 256>>>(ei1, pseudo1);
    gemmS_kernel<<<(N1 + 63) / 64, 256>>>(W2, root2);
    {
        dim3 g(16, 8);
        fc1_kernel<<<g, 256>>>(fc1_w, b2);
    }
    fc2_kernel<<<100, 320>>>(fc1_b, fc2_w, fc2_b, out);
}

// round 16
// speedup vs baseline: 1.1046x; 1.1046x over previous
#include <cuda_runtime.h>
#include <math.h>

#define N0 78400      // B*28*28
#define N1 19600      // B*14*14
#define E0 627200
#define E1 156800
#define C1 32
#define C2 64
#define P2SZ 313600   // 25*14*14*64
#define TW 26         // 25 tap cols + 1 degree col
#define SK 800        // S row width: 25 taps * 32 cin

__device__ float g_T[N0 * TW];             // layer-1 tap accumulator (+deg)
__device__ float g_pool1[N1 * C1];
__device__ float g_S[N1 * SK];             // layer-2 scattered tap features
__device__ float g_agg1[N1 * C2];          // gemmS output (deg-divided, root added)
__device__ float g_deg1[N1];
__device__ float g_pool2[P2SZ];
__device__ float g_fc1[100 * 512];

__device__ __forceinline__ float elu1(float v) {
    return v > 0.f ? v : (expf(v) - 1.f);
}

// ---- packed f32x2 helpers (sm_100+) ----
__device__ __forceinline__ void ffma2(unsigned long long &d,
                                      unsigned long long a,
                                      unsigned long long b) {
    asm("fma.rn.f32x2 %0, %1, %2, %0;" : "+l"(d) : "l"(a), "l"(b));
}
__device__ __forceinline__ unsigned long long dup2(float v) {
    unsigned long long r; unsigned int u = __float_as_uint(v);
    asm("mov.b64 %0, {%1, %1};" : "=l"(r) : "r"(u));
    return r;
}
__device__ __forceinline__ float2 ull2f2(unsigned long long u) {
    float2 r;
    asm("mov.b64 {%0, %1}, %2;" : "=f"(r.x), "=f"(r.y) : "l"(u));
    return r;
}
// Vectored no-return reduction (sm_90+): 8B atomic add of a float pair.
__device__ __forceinline__ void red_add_v2(float* p, float a, float b) {
    asm volatile("red.global.add.v2.f32 [%0], {%1, %2};"
                 :: "l"(p), "f"(a), "f"(b) : "memory");
}

// Zeroing split into 3 launches so edge1 lands in the ncu capture slot (#4).
__global__ void zeroT_kernel() {
    int stride = gridDim.x * blockDim.x;
    int t0 = blockIdx.x * blockDim.x + threadIdx.x;
    float4 z = make_float4(0.f, 0.f, 0.f, 0.f);
    float4* T4 = (float4*)g_T;
    for (int i = t0; i < (N0 * TW) / 4; i += stride) T4[i] = z;
}
__global__ void zeroS_kernel() {
    int stride = gridDim.x * blockDim.x;
    int t0 = blockIdx.x * blockDim.x + threadIdx.x;
    float4 z = make_float4(0.f, 0.f, 0.f, 0.f);
    float4* S4 = (float4*)g_S;
    for (int i = t0; i < (N1 * SK) / 4; i += stride) S4[i] = z;
}
__global__ void zeroMisc_kernel() {
    int stride = gridDim.x * blockDim.x;
    int t0 = blockIdx.x * blockDim.x + threadIdx.x;
    float4 z = make_float4(0.f, 0.f, 0.f, 0.f);
    float4* D4 = (float4*)g_deg1;
    float4* F4 = (float4*)g_fc1;
    for (int i = t0; i < N1 / 4; i += stride) D4[i] = z;
    for (int i = t0; i < (100 * 512) / 4; i += stride) F4[i] = z;
}

// Layer-1 edges, factorized (Cin=1): scatter x[s]-scaled tap weights into T[dst].
__global__ void edge1_kernel(const float* __restrict__ x,
                             const int* __restrict__ ei,
                             const float* __restrict__ ps) {
    int e = blockIdx.x * blockDim.x + threadIdx.x;
    if (e >= E0) return;
    int s = ei[e];
    int d = ei[E0 + e];
    float xv = __ldg(x + s);
    float2 pv = ((const float2*)ps)[e];
    float px = pv.x * 4.f;
    float py = pv.y * 4.f;
    float fxf = floorf(px), fyf = floorf(py);
    float fx = px - fxf, fy = py - fyf;
    int kx0 = min((int)fxf, 4), ky0 = min((int)fyf, 4);
    int kx1 = min(kx0 + 1, 4), ky1 = min(ky0 + 1, 4);
    float* Tb = g_T + d * TW;
    atomicAdd(Tb + kx0 * 5 + ky0, xv * (1.f - fx) * (1.f - fy));
    atomicAdd(Tb + kx0 * 5 + ky1, xv * (1.f - fx) * fy);
    atomicAdd(Tb + kx1 * 5 + ky0, xv * fx * (1.f - fy));
    atomicAdd(Tb + kx1 * 5 + ky1, xv * fx * fy);
    atomicAdd(Tb + 25, 1.f);
}

// Fused: T@W1 (25x32) + deg-normalize + root + bias + 2x2 maxpool + ELU -> pool1
__global__ void pool1_kernel(const float* __restrict__ x,
                             const float* __restrict__ W1,
                             const float* __restrict__ root1,
                             const float* __restrict__ b1) {
    __shared__ float sW[25 * C1];
    for (int i = threadIdx.x; i < 25 * C1; i += blockDim.x) sW[i] = W1[i];
    __syncthreads();

    int tid = blockIdx.x * blockDim.x + threadIdx.x;
    if (tid >= N1 * C1) return;
    int ch = tid & 31;
    int p = tid >> 5;
    int pc = p % 14;
    int pr = (p / 14) % 14;
    int b = p / 196;
    float r1 = root1[ch];
    float bias = b1[ch];
    float m = -1e30f;
#pragma unroll
    for (int dr = 0; dr < 2; dr++)
#pragma unroll
        for (int dc = 0; dc < 2; dc++) {
            int n = b * 784 + (2 * pr + dr) * 28 + (2 * pc + dc);
            const float* Tr = g_T + n * TW;
            float deg = fmaxf(Tr[25], 1.f);
            float acc = 0.f;
#pragma unroll
            for (int k = 0; k < 25; k++) acc += Tr[k] * sW[k * C1 + ch];
            float v = acc / deg + x[n] * r1 + bias;
            m = fmaxf(m, v);
        }
    g_pool1[p * C1 + ch] = elu1(m);
}

// Layer-2 edges: 16 threads per edge, thread = cin pair. Scatter tap-weighted
// pool1[src] rows into S[dst] via red.v2 (half the REDG issue of scalar).
__global__ void scatter2_kernel(const int* __restrict__ ei,
                                const float* __restrict__ ps) {
    int gt = blockIdx.x * blockDim.x + threadIdx.x;
    int e = gt >> 4;
    int h = gt & 15;          // cin pair index: channels 2h, 2h+1
    if (e >= E1) return;
    int s = ei[e];
    int d = ei[E1 + e];
    float2 pv = ((const float2*)ps)[e];
    float px = pv.x * 4.f;
    float py = pv.y * 4.f;
    float fxf = floorf(px), fyf = floorf(py);
    float fx = px - fxf, fy = py - fyf;
    int kx0 = min((int)fxf, 4), ky0 = min((int)fyf, 4);
    int kx1 = min(kx0 + 1, 4), ky1 = min(ky0 + 1, 4);
    float w00 = (1.f - fx) * (1.f - fy);
    float w01 = (1.f - fx) * fy;
    float w10 = fx * (1.f - fy);
    float w11 = fx * fy;
    float2 xv = *(const float2*)(g_pool1 + s * C1 + 2 * h);
    float* Sb = g_S + d * SK + 2 * h;
    red_add_v2(Sb + (kx0 * 5 + ky0) * 32, xv.x * w00, xv.y * w00);
    red_add_v2(Sb + (kx0 * 5 + ky1) * 32, xv.x * w01, xv.y * w01);
    red_add_v2(Sb + (kx1 * 5 + ky0) * 32, xv.x * w10, xv.y * w10);
    red_add_v2(Sb + (kx1 * 5 + ky1) * 32, xv.x * w11, xv.y * w11);
    if (h == 0) atomicAdd(&g_deg1[d], 1.f);
}

// agg1[19600x64] = S[19600x800] @ W2flat[800x64] / deg + pool1 @ root2
// m-tile 64, 256 threads, thread = 4m x 4n, packed f32x2 FMA.
__global__ void __launch_bounds__(256) gemmS_kernel(const float* __restrict__ W2,
                                                    const float* __restrict__ root2) {
    __shared__ float As[32 * 68];   // [k][m], stride 68 (16B-aligned rows)
    __shared__ float Bs[32 * 64];   // [k][n]
    int tid = threadIdx.x;
    int m0 = blockIdx.x * 64;
    int tm = tid >> 4;       // 0..15 -> m rows tm*4..tm*4+3
    int tn = tid & 15;       // 0..15 -> n cols tn*4..tn*4+3

    unsigned long long accm[2][4], accr[2][4];
#pragma unroll
    for (int p = 0; p < 2; p++)
#pragma unroll
        for (int j = 0; j < 4; j++) { accm[p][j] = 0ull; accr[p][j] = 0ull; }

    // 25 chunks over S/W2, then 1 chunk over pool1/root2 (into accr).
    for (int c = 0; c < 26; c++) {
        __syncthreads();
        if (c < 25) {
            int k0 = c * 32;
            for (int idx = tid; idx < 64 * 32; idx += 256) {
                int r = idx >> 5, k = idx & 31;
                int row = min(m0 + r, N1 - 1);
                As[k * 68 + r] = g_S[row * SK + k0 + k];
            }
            for (int idx = tid; idx < 32 * 64; idx += 256) {
                int k = idx >> 6, nn = idx & 63;
                Bs[k * 64 + nn] = W2[(k0 + k) * 64 + nn];
            }
        } else {
            for (int idx = tid; idx < 64 * 32; idx += 256) {
                int r = idx >> 5, k = idx & 31;
                int row = min(m0 + r, N1 - 1);
                As[k * 68 + r] = g_pool1[row * C1 + k];
            }
            for (int idx = tid; idx < 32 * 64; idx += 256) {
                int k = idx >> 6, nn = idx & 63;
                Bs[k * 64 + nn] = root2[k * 64 + nn];
            }
        }
        __syncthreads();
        unsigned long long (*acc)[4] = (c < 25) ? accm : accr;
#pragma unroll
        for (int k = 0; k < 32; k++) {
            ulonglong2 a = *(const ulonglong2*)&As[k * 68 + tm * 4];
            float4 b = *(const float4*)&Bs[k * 64 + tn * 4];
            unsigned long long bd[4] = {dup2(b.x), dup2(b.y), dup2(b.z), dup2(b.w)};
#pragma unroll
            for (int j = 0; j < 4; j++) {
                ffma2(acc[0][j], a.x, bd[j]);
                ffma2(acc[1][j], a.y, bd[j]);
            }
        }
    }

    // epilogue: rows tm*4+2p (lo) and tm*4+2p+1 (hi); out = accm/deg + accr
#pragma unroll
    for (int p = 0; p < 2; p++) {
        int r0 = m0 + tm * 4 + 2 * p;
        if (r0 >= N1) break;
        float d0 = 1.f / fmaxf(g_deg1[r0], 1.f);
        float d1 = (r0 + 1 < N1) ? 1.f / fmaxf(g_deg1[r0 + 1], 1.f) : 1.f;
        float2 m0f = ull2f2(accm[p][0]), m1f = ull2f2(accm[p][1]);
        float2 m2f = ull2f2(accm[p][2]), m3f = ull2f2(accm[p][3]);
        float2 r0f = ull2f2(accr[p][0]), r1f = ull2f2(accr[p][1]);
        float2 r2f = ull2f2(accr[p][2]), r3f = ull2f2(accr[p][3]);
        float4 lo = make_float4(m0f.x * d0 + r0f.x, m1f.x * d0 + r1f.x,
                                m2f.x * d0 + r2f.x, m3f.x * d0 + r3f.x);
        float4 hi = make_float4(m0f.y * d1 + r0f.y, m1f.y * d1 + r1f.y,
                                m2f.y * d1 + r2f.y, m3f.y * d1 + r3f.y);
        *(float4*)&g_agg1[r0 * C2 + tn * 4] = lo;
        if (r0 + 1 < N1)
            *(float4*)&g_agg1[(r0 + 1) * C2 + tn * 4] = hi;
    }
}

// Node epilogue conv2: bias + maxpool (+ reference's [25,28,28,64] reshape) + ELU
__global__ void pool2_kernel(const float* __restrict__ b2) {
    int tid = blockIdx.x * blockDim.x + threadIdx.x;
    if (tid >= P2SZ) return;
    int ch = tid & 63;
    int p = tid >> 6;
    int pc = p % 14;
    int pr = (p / 14) % 14;
    int bb = p / 196;
    float bias = b2[ch];
    float m = -1e30f;
#pragma unroll
    for (int dr = 0; dr < 2; dr++)
#pragma unroll
        for (int dc = 0; dc < 2; dc++) {
            int n = bb * 784 + (2 * pr + dr) * 28 + (2 * pc + dc);
            m = fmaxf(m, g_agg1[n * C2 + ch] + bias);
        }
    g_pool2[tid] = elu1(m);
}

// fc1: M=100, N=512, K=3136. Register-tiled, k-split with atomic accumulation.
__global__ void fc1_kernel(const float* __restrict__ w) {
    __shared__ float sin_s[100 * 56];
    __shared__ float sw_s[56 * 32];
    int tid = threadIdx.x;
    int jl = tid & 31;
    int mg = tid >> 5;
    int j0 = blockIdx.x * 32;
    int kbase = blockIdx.y * 392;

    float acc[13];
#pragma unroll
    for (int i = 0; i < 13; i++) acc[i] = 0.f;

    for (int c = 0; c < 7; c++) {
        int k0 = kbase + c * 56;
        __syncthreads();
        for (int idx = tid; idx < 100 * 56; idx += 256) {
            int m = idx / 56, kk = idx % 56;
            sin_s[idx] = g_pool2[m * 3136 + k0 + kk];
        }
        for (int idx = tid; idx < 56 * 32; idx += 256) {
            int kk = idx >> 5, jj = idx & 31;
            sw_s[idx] = w[(k0 + kk) * 512 + j0 + jj];
        }
        __syncthreads();
#pragma unroll
        for (int q = 0; q < 14; q++) {
            float w0 = sw_s[(q * 4 + 0) * 32 + jl];
            float w1 = sw_s[(q * 4 + 1) * 32 + jl];
            float w2 = sw_s[(q * 4 + 2) * 32 + jl];
            float w3 = sw_s[(q * 4 + 3) * 32 + jl];
#pragma unroll
            for (int mi = 0; mi < 13; mi++) {
                int m = mg * 13 + mi;
                float4 s4 = *(const float4*)&sin_s[m * 56 + q * 4];
                acc[mi] += s4.x * w0 + s4.y * w1 + s4.z * w2 + s4.w * w3;
            }
        }
    }
#pragma unroll
    for (int mi = 0; mi < 13; mi++) {
        int m = mg * 13 + mi;
        if (m < 100) atomicAdd(&g_fc1[m * 512 + j0 + jl], acc[mi]);
    }
}

// Block per batch row: stage elu(fc1+bias) in smem, 10 warps -> logits, log_softmax.
__global__ void fc2_kernel(const float* __restrict__ b1v,
                           const float* __restrict__ w,
                           const float* __restrict__ b,
                           float* __restrict__ out) {
    __shared__ float sx[512];
    __shared__ float sh[10];
    int m = blockIdx.x;
    int tid = threadIdx.x;
    for (int i = tid; i < 512; i += 320)
        sx[i] = elu1(g_fc1[m * 512 + i] + b1v[i]);
    __syncthreads();
    int warp = tid >> 5;
    int lane = tid & 31;
    if (warp < 10) {
        float acc = 0.f;
        for (int i = lane; i < 512; i += 32)
            acc += sx[i] * w[i * 10 + warp];
#pragma unroll
        for (int o = 16; o > 0; o >>= 1)
            acc += __shfl_down_sync(0xffffffffu, acc, o);
        if (lane == 0) sh[warp] = elu1(acc + b[warp]);
    }
    __syncthreads();
    if (tid == 0) {
        float mx = sh[0];
        for (int c = 1; c < 10; c++) mx = fmaxf(mx, sh[c]);
        float s = 0.f;
        for (int c = 0; c < 10; c++) s += expf(sh[c] - mx);
        float lse = mx + logf(s);
        for (int c = 0; c < 10; c++) out[m * 10 + c] = sh[c] - lse;
    }
}

extern "C" void kernel_launch(void* const* d_in, const int* in_sizes, int n_in,
                              void* d_out, int out_size) {
    const float* x       = (const float*)d_in[0];
    const float* pseudo0 = (const float*)d_in[1];
    const float* pseudo1 = (const float*)d_in[2];
    const float* W1      = (const float*)d_in[3];
    const float* root1   = (const float*)d_in[4];
    const float* b1      = (const float*)d_in[5];
    const float* W2      = (const float*)d_in[6];
    const float* root2   = (const float*)d_in[7];
    const float* b2      = (const float*)d_in[8];
    const float* fc1_w   = (const float*)d_in[9];
    const float* fc1_b   = (const float*)d_in[10];
    const float* fc2_w   = (const float*)d_in[11];
    const float* fc2_b   = (const float*)d_in[12];
    const int* ei0       = (const int*)d_in[13];
    const int* ei1       = (const int*)d_in[14];
    float* out = (float*)d_out;

    zeroT_kernel<<<512, 256>>>();
    zeroS_kernel<<<1024, 256>>>();
    zeroMisc_kernel<<<64, 256>>>();
    edge1_kernel<<<(E0 + 255) / 256, 256>>>(x, ei0, pseudo0);   // ncu slot #4
    pool1_kernel<<<(N1 * C1 + 255) / 256, 256>>>(x, W1, root1, b1);
    scatter2_kernel<<<(E1 * 16 + 255) / 256, 256>>>(ei1, pseudo1);
    gemmS_kernel<<<(N1 + 63) / 64, 256>>>(W2, root2);
    pool2_kernel<<<(P2SZ + 255) / 256, 256>>>(b2);
    {
        dim3 g(16, 8);
        fc1_kernel<<<g, 256>>>(fc1_w);
    }
    fc2_kernel<<<100, 320>>>(fc1_b, fc2_w, fc2_b, out);
}